// round 2
// baseline (speedup 1.0000x reference)
#include <cuda_runtime.h>
#include <cuda_bf16.h>
#include <math.h>

// Problem constants
#define Bb 4
#define Tt 2048
#define Cc 1024
#define Hh 16
#define Dd 64
#define MROWS (Bb*Tt)          // 8192
#define N_QKV (3*Cc)           // 3072

// Scratch (allocation-free rule: __device__ globals)
__device__ float g_qkv[(size_t)MROWS * N_QKV];   // 96 MB
__device__ float g_y[(size_t)MROWS * Cc];        // 32 MB

// ---------------------------------------------------------------------------
// SGEMM: C[M,N] = A[M,K] @ B[K,N], all row-major fp32.
// 128x128 tile, BK=8, 256 threads, 8x8 microtile.
// ---------------------------------------------------------------------------
#define BM 128
#define BN 128
#define BK 8

__global__ __launch_bounds__(256) void sgemm_kernel(
    const float* __restrict__ A, const float* __restrict__ B,
    float* __restrict__ C, int M, int N, int K)
{
    __shared__ float As[BK][BM];
    __shared__ float Bs[BK][BN];

    const int tid = threadIdx.x;
    const int bm = blockIdx.y * BM;
    const int bn = blockIdx.x * BN;

    const int arow = tid >> 1;            // 0..127
    const int acol = (tid & 1) * 4;       // 0 or 4
    const int brow = tid >> 5;            // 0..7
    const int bcol = (tid & 31) * 4;      // 0..124

    const int tx = (tid & 15) * 8;
    const int ty = (tid >> 4) * 8;

    float acc[8][8];
#pragma unroll
    for (int i = 0; i < 8; i++)
#pragma unroll
        for (int j = 0; j < 8; j++) acc[i][j] = 0.f;

    const float* Ap = A + (size_t)(bm + arow) * K + acol;
    const float* Bp = B + (size_t)brow * N + bn + bcol;

    for (int k0 = 0; k0 < K; k0 += BK) {
        float4 av = *(const float4*)(Ap + k0);
        As[acol + 0][arow] = av.x;
        As[acol + 1][arow] = av.y;
        As[acol + 2][arow] = av.z;
        As[acol + 3][arow] = av.w;
        *(float4*)&Bs[brow][bcol] = *(const float4*)(Bp + (size_t)k0 * N);
        __syncthreads();

#pragma unroll
        for (int k = 0; k < BK; k++) {
            float a[8], b[8];
            *(float4*)(a)     = *(const float4*)&As[k][ty];
            *(float4*)(a + 4) = *(const float4*)&As[k][ty + 4];
            *(float4*)(b)     = *(const float4*)&Bs[k][tx];
            *(float4*)(b + 4) = *(const float4*)&Bs[k][tx + 4];
#pragma unroll
            for (int i = 0; i < 8; i++)
#pragma unroll
                for (int j = 0; j < 8; j++)
                    acc[i][j] = fmaf(a[i], b[j], acc[i][j]);
        }
        __syncthreads();
    }

#pragma unroll
    for (int i = 0; i < 8; i++) {
        float* Crow = C + (size_t)(bm + ty + i) * N + bn + tx;
#pragma unroll
        for (int j = 0; j < 8; j += 4) {
            float4 v = make_float4(acc[i][j], acc[i][j+1], acc[i][j+2], acc[i][j+3]);
            *(float4*)(Crow + j) = v;
        }
    }
}

// ---------------------------------------------------------------------------
// Flash attention (causal), fp32.
// Grid: (T/AQ, B*H). Block: 128 threads; thread t owns query row qt*AQ + t.
// KV tiles of 64 keys. q[64] and acc[64] in registers; scores staged in smem.
// Dynamic smem: ks 64*64 + vs 64*64 + ss 64*128 floats = 64 KB.
// ---------------------------------------------------------------------------
#define AQ 128
#define AK 64

__global__ __launch_bounds__(128) void attn_kernel(
    const float* __restrict__ qkv, float* __restrict__ y)
{
    extern __shared__ float sm[];
    float* ks = sm;                 // [64][64]
    float* vs = sm + AK * Dd;       // [64][64]
    float* ss = sm + 2 * AK * Dd;   // [64][128]

    const int tid = threadIdx.x;
    const int qt  = blockIdx.x;
    const int bh  = blockIdx.y;
    const int b   = bh >> 4;
    const int h   = bh & 15;
    const int qidx = qt * AQ + tid;

    // load q (scaled by 1/sqrt(D) = 0.125)
    const float* qrow = qkv + ((size_t)(b * Tt + qidx)) * N_QKV + h * Dd;
    float q[Dd];
#pragma unroll
    for (int d = 0; d < Dd; d += 4) {
        float4 v = *(const float4*)(qrow + d);
        q[d]   = v.x * 0.125f;
        q[d+1] = v.y * 0.125f;
        q[d+2] = v.z * 0.125f;
        q[d+3] = v.w * 0.125f;
    }

    float acc[Dd];
#pragma unroll
    for (int d = 0; d < Dd; d++) acc[d] = 0.f;
    float m = -1e30f, l = 0.f;

    const int nkt = 2 * qt + 2;   // key tiles covering keys < (qt+1)*128

    for (int kt = 0; kt < nkt; kt++) {
        __syncthreads();
        {
            // cooperative load K,V tiles: 64 rows x 64 cols each
            int r  = tid >> 1;
            int c0 = (tid & 1) * 32;
            int kglob = kt * AK + r;
            const float* krow = qkv + ((size_t)(b * Tt + kglob)) * N_QKV + Cc + h * Dd + c0;
            const float* vrow = krow + Cc;
#pragma unroll
            for (int c = 0; c < 32; c += 4) {
                *(float4*)&ks[r * Dd + c0 + c] = *(const float4*)(krow + c);
                *(float4*)&vs[r * Dd + c0 + c] = *(const float4*)(vrow + c);
            }
        }
        __syncthreads();

        const bool diag = (kt >= 2 * qt);
        float mt = -1e30f;

#pragma unroll 1
        for (int j = 0; j < AK; j++) {
            const float4* k4 = (const float4*)&ks[j * Dd];
            float s0 = 0.f, s1 = 0.f, s2 = 0.f, s3 = 0.f;
#pragma unroll
            for (int d4 = 0; d4 < 16; d4++) {
                float4 kk = k4[d4];
                s0 = fmaf(q[d4*4+0], kk.x, s0);
                s1 = fmaf(q[d4*4+1], kk.y, s1);
                s2 = fmaf(q[d4*4+2], kk.z, s2);
                s3 = fmaf(q[d4*4+3], kk.w, s3);
            }
            float s = (s0 + s1) + (s2 + s3);
            if (diag && (kt * AK + j > qidx)) s = -1e30f;
            ss[j * AQ + tid] = s;
            mt = fmaxf(mt, s);
        }

        float mnew  = fmaxf(m, mt);
        float scale = __expf(m - mnew);
        l *= scale;
#pragma unroll
        for (int d = 0; d < Dd; d++) acc[d] *= scale;

#pragma unroll 1
        for (int j = 0; j < AK; j++) {
            float p = __expf(ss[j * AQ + tid] - mnew);
            l += p;
            const float4* v4 = (const float4*)&vs[j * Dd];
#pragma unroll
            for (int d4 = 0; d4 < 16; d4++) {
                float4 vv = v4[d4];
                acc[d4*4+0] = fmaf(p, vv.x, acc[d4*4+0]);
                acc[d4*4+1] = fmaf(p, vv.y, acc[d4*4+1]);
                acc[d4*4+2] = fmaf(p, vv.z, acc[d4*4+2]);
                acc[d4*4+3] = fmaf(p, vv.w, acc[d4*4+3]);
            }
        }
        m = mnew;
    }

    float inv = 1.f / l;
    float* yrow = y + ((size_t)(b * Tt + qidx)) * Cc + h * Dd;
#pragma unroll
    for (int d = 0; d < Dd; d += 4) {
        float4 v = make_float4(acc[d] * inv, acc[d+1] * inv, acc[d+2] * inv, acc[d+3] * inv);
        *(float4*)(yrow + d) = v;
    }
}

// ---------------------------------------------------------------------------
// Launch
// ---------------------------------------------------------------------------
extern "C" void kernel_launch(void* const* d_in, const int* in_sizes, int n_in,
                              void* d_out, int out_size)
{
    const float* x     = (const float*)d_in[0];   // (B,T,C)
    const float* Wqkv  = (const float*)d_in[1];   // (C,3C)
    const float* Wproj = (const float*)d_in[2];   // (C,C)
    float* out = (float*)d_out;                   // (B,T,C)

    // Set attributes / resolve symbols first (all capture-legal, no allocs).
    const int attn_smem = (2 * AK * Dd + AK * AQ) * sizeof(float);  // 64 KB
    cudaFuncSetAttribute(attn_kernel, cudaFuncAttributeMaxDynamicSharedMemorySize, attn_smem);

    float *d_qkv, *d_y;
    cudaGetSymbolAddress((void**)&d_qkv, g_qkv);
    cudaGetSymbolAddress((void**)&d_y, g_y);

    // 1) QKV GEMM: (8192,1024) @ (1024,3072)
    {
        dim3 grid(N_QKV / BN, MROWS / BM);
        sgemm_kernel<<<grid, 256>>>(x, Wqkv, d_qkv, MROWS, N_QKV, Cc);
    }

    // 2) causal flash attention
    {
        dim3 grid(Tt / AQ, Bb * Hh);
        attn_kernel<<<grid, 128, attn_smem>>>(d_qkv, d_y);
    }

    // 3) projection GEMM: (8192,1024) @ (1024,1024)
    {
        dim3 grid(Cc / BN, MROWS / BM);
        sgemm_kernel<<<grid, 256>>>(d_y, Wproj, out, MROWS, Cc, Cc);
    }
}

// round 3
// speedup vs baseline: 1.3970x; 1.3970x over previous
#include <cuda_runtime.h>
#include <cuda_bf16.h>
#include <math.h>
#include <stdint.h>

// Problem constants
#define Bb 4
#define Tt 2048
#define Cc 1024
#define Hh 16
#define Dd 64
#define MROWS (Bb*Tt)          // 8192
#define N_QKV (3*Cc)           // 3072

// Scratch (__device__ globals: allocation-free rule)
__device__ float g_qkv[(size_t)MROWS * N_QKV];        // 96 MB
__device__ float g_y[(size_t)MROWS * Cc];             // 32 MB
__device__ __nv_bfloat16 g_ah[(size_t)MROWS * Cc];    // 16 MB
__device__ __nv_bfloat16 g_al[(size_t)MROWS * Cc];    // 16 MB
__device__ __nv_bfloat16 g_bh[(size_t)Cc * N_QKV];    // 6 MB
__device__ __nv_bfloat16 g_bl[(size_t)Cc * N_QKV];    // 6 MB

// ---------------------------------------------------------------------------
// fp32 -> bf16 hi/lo split (elementwise, float4 vectorized)
// ---------------------------------------------------------------------------
__global__ __launch_bounds__(256) void split_kernel(
    const float* __restrict__ in,
    __nv_bfloat16* __restrict__ hi, __nv_bfloat16* __restrict__ lo, int n4)
{
    int i = blockIdx.x * blockDim.x + threadIdx.x;
    if (i >= n4) return;
    float4 v = ((const float4*)in)[i];
    float vv[4] = {v.x, v.y, v.z, v.w};
    __nv_bfloat16 h[4], l[4];
#pragma unroll
    for (int j = 0; j < 4; j++) {
        h[j] = __float2bfloat16(vv[j]);
        l[j] = __float2bfloat16(vv[j] - __bfloat162float(h[j]));
    }
    ((uint2*)hi)[i] = *(uint2*)h;
    ((uint2*)lo)[i] = *(uint2*)l;
}

// ---------------------------------------------------------------------------
// bf16x3 split GEMM: C[M,N] = Ah@Bh + Ah@Bl + Al@Bh  (fp32 accumulate)
// 128x128x32 tiles, 256 threads / 8 warps (64x32 warp tile), cp.async double
// buffer, mma.sync.m16n8k16.
// ---------------------------------------------------------------------------
#define GBM 128
#define GBN 128
#define GBK 32
#define ASTR 40    // 32 + 8 pad (bf16 elems) -> conflict-free LDSM
#define BSTR 136   // 128 + 8 pad
#define SA_SZ (GBM*ASTR)   // 5120 elems
#define SB_SZ (GBK*BSTR)   // 4352 elems
// dyn smem: 2 bufs * (sAh + sAl + sBh + sBl) = (4*SA_SZ + 4*SB_SZ)*2B = 75776

__device__ __forceinline__ void cp16(void* s, const void* g) {
    uint32_t sa = (uint32_t)__cvta_generic_to_shared(s);
    asm volatile("cp.async.cg.shared.global [%0], [%1], 16;" :: "r"(sa), "l"(g));
}
__device__ __forceinline__ void ldsm4(uint32_t* r, const __nv_bfloat16* p) {
    uint32_t a = (uint32_t)__cvta_generic_to_shared(p);
    asm volatile("ldmatrix.sync.aligned.m8n8.x4.shared.b16 {%0,%1,%2,%3}, [%4];"
        : "=r"(r[0]), "=r"(r[1]), "=r"(r[2]), "=r"(r[3]) : "r"(a));
}
__device__ __forceinline__ void ldsm2t(uint32_t* r, const __nv_bfloat16* p) {
    uint32_t a = (uint32_t)__cvta_generic_to_shared(p);
    asm volatile("ldmatrix.sync.aligned.m8n8.x2.trans.shared.b16 {%0,%1}, [%2];"
        : "=r"(r[0]), "=r"(r[1]) : "r"(a));
}
__device__ __forceinline__ void mma16816(float* c, const uint32_t* a, const uint32_t* b) {
    asm volatile("mma.sync.aligned.m16n8k16.row.col.f32.bf16.bf16.f32 "
        "{%0,%1,%2,%3}, {%4,%5,%6,%7}, {%8,%9}, {%0,%1,%2,%3};"
        : "+f"(c[0]), "+f"(c[1]), "+f"(c[2]), "+f"(c[3])
        : "r"(a[0]), "r"(a[1]), "r"(a[2]), "r"(a[3]), "r"(b[0]), "r"(b[1]));
}

__global__ __launch_bounds__(256) void gemm_bf16x3(
    const __nv_bfloat16* __restrict__ Ah, const __nv_bfloat16* __restrict__ Al,
    const __nv_bfloat16* __restrict__ Bh, const __nv_bfloat16* __restrict__ Bl,
    float* __restrict__ C, int M, int N, int K)
{
    extern __shared__ __nv_bfloat16 smraw[];
    __nv_bfloat16* sAh = smraw;                     // [2][SA_SZ]
    __nv_bfloat16* sAl = smraw + 2 * SA_SZ;         // [2][SA_SZ]
    __nv_bfloat16* sBh = smraw + 4 * SA_SZ;         // [2][SB_SZ]
    __nv_bfloat16* sBl = smraw + 4 * SA_SZ + 2 * SB_SZ;

    const int tid  = threadIdx.x;
    const int bm   = blockIdx.y * GBM;
    const int bn   = blockIdx.x * GBN;
    const int lane = tid & 31;
    const int warp = tid >> 5;
    const int wm   = (warp & 1) * 64;
    const int wn   = (warp >> 1) * 32;

    // cooperative load mapping
    const int ar = tid >> 1, aq = tid & 1;   // A: 128 rows x (2 x 16-col halves)
    const int br = tid >> 3, bq = tid & 7;   // B: 32 rows x (8 x 16-col chunks)

    float acc[4][4][4];
#pragma unroll
    for (int i = 0; i < 4; i++)
#pragma unroll
        for (int j = 0; j < 4; j++)
#pragma unroll
            for (int t = 0; t < 4; t++) acc[i][j][t] = 0.f;

    const int nkt = K / GBK;

#define LOAD_TILE(K0, S)                                                         \
    {                                                                            \
        const size_t ga = (size_t)(bm + ar) * K + (K0) + aq * 16;                \
        __nv_bfloat16* dAh = sAh + (S) * SA_SZ + ar * ASTR + aq * 16;            \
        __nv_bfloat16* dAl = sAl + (S) * SA_SZ + ar * ASTR + aq * 16;            \
        cp16(dAh,     Ah + ga);                                                  \
        cp16(dAh + 8, Ah + ga + 8);                                              \
        cp16(dAl,     Al + ga);                                                  \
        cp16(dAl + 8, Al + ga + 8);                                              \
        const size_t gb = (size_t)((K0) + br) * N + bn + bq * 16;                \
        __nv_bfloat16* dBh = sBh + (S) * SB_SZ + br * BSTR + bq * 16;            \
        __nv_bfloat16* dBl = sBl + (S) * SB_SZ + br * BSTR + bq * 16;            \
        cp16(dBh,     Bh + gb);                                                  \
        cp16(dBh + 8, Bh + gb + 8);                                              \
        cp16(dBl,     Bl + gb);                                                  \
        cp16(dBl + 8, Bl + gb + 8);                                              \
    }

    LOAD_TILE(0, 0);
    asm volatile("cp.async.commit_group;");

    for (int kt = 0; kt < nkt; kt++) {
        const int cur = kt & 1;
        const bool has_next = (kt + 1 < nkt);
        if (has_next) {
            LOAD_TILE((kt + 1) * GBK, cur ^ 1);
            asm volatile("cp.async.commit_group;");
            asm volatile("cp.async.wait_group 1;");
        } else {
            asm volatile("cp.async.wait_group 0;");
        }
        __syncthreads();

        const __nv_bfloat16* pAh = sAh + cur * SA_SZ;
        const __nv_bfloat16* pAl = sAl + cur * SA_SZ;
        const __nv_bfloat16* pBh = sBh + cur * SB_SZ;
        const __nv_bfloat16* pBl = sBl + cur * SB_SZ;

#pragma unroll
        for (int ks = 0; ks < 2; ks++) {
            uint32_t afh[4][4], afl[4][4], bfh[4][2], bfl[4][2];
            const int arow = lane & 15;
            const int acol = ks * 16 + (lane >> 4) * 8;
#pragma unroll
            for (int mt = 0; mt < 4; mt++) {
                const int off = (wm + mt * 16 + arow) * ASTR + acol;
                ldsm4(afh[mt], pAh + off);
                ldsm4(afl[mt], pAl + off);
            }
            const int brow = ks * 16 + (lane & 15);
#pragma unroll
            for (int nt = 0; nt < 4; nt++) {
                const int off = brow * BSTR + wn + nt * 8;
                ldsm2t(bfh[nt], pBh + off);
                ldsm2t(bfl[nt], pBl + off);
            }
#pragma unroll
            for (int mt = 0; mt < 4; mt++)
#pragma unroll
                for (int nt = 0; nt < 4; nt++) {
                    mma16816(acc[mt][nt], afh[mt], bfh[nt]);
                    mma16816(acc[mt][nt], afh[mt], bfl[nt]);
                    mma16816(acc[mt][nt], afl[mt], bfh[nt]);
                }
        }
        __syncthreads();
    }

    // epilogue
#pragma unroll
    for (int mt = 0; mt < 4; mt++) {
        const int row = bm + wm + mt * 16 + (lane >> 2);
#pragma unroll
        for (int nt = 0; nt < 4; nt++) {
            const int col = bn + wn + nt * 8 + (lane & 3) * 2;
            *(float2*)&C[(size_t)row * N + col] =
                make_float2(acc[mt][nt][0], acc[mt][nt][1]);
            *(float2*)&C[(size_t)(row + 8) * N + col] =
                make_float2(acc[mt][nt][2], acc[mt][nt][3]);
        }
    }
#undef LOAD_TILE
}

// ---------------------------------------------------------------------------
// Flash attention (causal), fp32 — unchanged from round 0 baseline.
// ---------------------------------------------------------------------------
#define AQ 128
#define AK 64

__global__ __launch_bounds__(128) void attn_kernel(
    const float* __restrict__ qkv, float* __restrict__ y)
{
    extern __shared__ float smf[];
    float* ks = smf;
    float* vs = smf + AK * Dd;
    float* ss = smf + 2 * AK * Dd;

    const int tid = threadIdx.x;
    const int qt  = blockIdx.x;
    const int bh  = blockIdx.y;
    const int b   = bh >> 4;
    const int h   = bh & 15;
    const int qidx = qt * AQ + tid;

    const float* qrow = qkv + ((size_t)(b * Tt + qidx)) * N_QKV + h * Dd;
    float q[Dd];
#pragma unroll
    for (int d = 0; d < Dd; d += 4) {
        float4 v = *(const float4*)(qrow + d);
        q[d]   = v.x * 0.125f;
        q[d+1] = v.y * 0.125f;
        q[d+2] = v.z * 0.125f;
        q[d+3] = v.w * 0.125f;
    }

    float acc[Dd];
#pragma unroll
    for (int d = 0; d < Dd; d++) acc[d] = 0.f;
    float m = -1e30f, l = 0.f;

    const int nkt = 2 * qt + 2;

    for (int kt = 0; kt < nkt; kt++) {
        __syncthreads();
        {
            int r  = tid >> 1;
            int c0 = (tid & 1) * 32;
            int kglob = kt * AK + r;
            const float* krow = qkv + ((size_t)(b * Tt + kglob)) * N_QKV + Cc + h * Dd + c0;
            const float* vrow = krow + Cc;
#pragma unroll
            for (int c = 0; c < 32; c += 4) {
                *(float4*)&ks[r * Dd + c0 + c] = *(const float4*)(krow + c);
                *(float4*)&vs[r * Dd + c0 + c] = *(const float4*)(vrow + c);
            }
        }
        __syncthreads();

        const bool diag = (kt >= 2 * qt);
        float mt = -1e30f;

#pragma unroll 1
        for (int j = 0; j < AK; j++) {
            const float4* k4 = (const float4*)&ks[j * Dd];
            float s0 = 0.f, s1 = 0.f, s2 = 0.f, s3 = 0.f;
#pragma unroll
            for (int d4 = 0; d4 < 16; d4++) {
                float4 kk = k4[d4];
                s0 = fmaf(q[d4*4+0], kk.x, s0);
                s1 = fmaf(q[d4*4+1], kk.y, s1);
                s2 = fmaf(q[d4*4+2], kk.z, s2);
                s3 = fmaf(q[d4*4+3], kk.w, s3);
            }
            float s = (s0 + s1) + (s2 + s3);
            if (diag && (kt * AK + j > qidx)) s = -1e30f;
            ss[j * AQ + tid] = s;
            mt = fmaxf(mt, s);
        }

        float mnew  = fmaxf(m, mt);
        float scale = __expf(m - mnew);
        l *= scale;
#pragma unroll
        for (int d = 0; d < Dd; d++) acc[d] *= scale;

#pragma unroll 1
        for (int j = 0; j < AK; j++) {
            float p = __expf(ss[j * AQ + tid] - mnew);
            l += p;
            const float4* v4 = (const float4*)&vs[j * Dd];
#pragma unroll
            for (int d4 = 0; d4 < 16; d4++) {
                float4 vv = v4[d4];
                acc[d4*4+0] = fmaf(p, vv.x, acc[d4*4+0]);
                acc[d4*4+1] = fmaf(p, vv.y, acc[d4*4+1]);
                acc[d4*4+2] = fmaf(p, vv.z, acc[d4*4+2]);
                acc[d4*4+3] = fmaf(p, vv.w, acc[d4*4+3]);
            }
        }
        m = mnew;
    }

    float inv = 1.f / l;
    float* yrow = y + ((size_t)(b * Tt + qidx)) * Cc + h * Dd;
#pragma unroll
    for (int d = 0; d < Dd; d += 4) {
        float4 v = make_float4(acc[d] * inv, acc[d+1] * inv, acc[d+2] * inv, acc[d+3] * inv);
        *(float4*)(yrow + d) = v;
    }
}

// ---------------------------------------------------------------------------
// Launch
// ---------------------------------------------------------------------------
extern "C" void kernel_launch(void* const* d_in, const int* in_sizes, int n_in,
                              void* d_out, int out_size)
{
    const float* x     = (const float*)d_in[0];   // (B,T,C)
    const float* Wqkv  = (const float*)d_in[1];   // (C,3C)
    const float* Wproj = (const float*)d_in[2];   // (C,C)
    float* out = (float*)d_out;                   // (B,T,C)

    const int attn_smem = (2 * AK * Dd + AK * AQ) * sizeof(float);  // 64 KB
    const int gemm_smem = (4 * SA_SZ + 4 * SB_SZ) * sizeof(__nv_bfloat16);  // 75776
    cudaFuncSetAttribute(attn_kernel, cudaFuncAttributeMaxDynamicSharedMemorySize, attn_smem);
    cudaFuncSetAttribute(gemm_bf16x3, cudaFuncAttributeMaxDynamicSharedMemorySize, gemm_smem);

    float *d_qkv, *d_y;
    __nv_bfloat16 *d_ah, *d_al, *d_bh, *d_bl;
    cudaGetSymbolAddress((void**)&d_qkv, g_qkv);
    cudaGetSymbolAddress((void**)&d_y, g_y);
    cudaGetSymbolAddress((void**)&d_ah, g_ah);
    cudaGetSymbolAddress((void**)&d_al, g_al);
    cudaGetSymbolAddress((void**)&d_bh, g_bh);
    cudaGetSymbolAddress((void**)&d_bl, g_bl);

    // 1) split x and Wqkv to bf16 hi/lo
    {
        int n4 = MROWS * Cc / 4;
        split_kernel<<<(n4 + 255) / 256, 256>>>(x, d_ah, d_al, n4);
        int w4 = Cc * N_QKV / 4;
        split_kernel<<<(w4 + 255) / 256, 256>>>(Wqkv, d_bh, d_bl, w4);
    }

    // 2) QKV GEMM (tensor cores): (8192,1024) @ (1024,3072) -> fp32 qkv
    {
        dim3 grid(N_QKV / GBN, MROWS / GBM);
        gemm_bf16x3<<<grid, 256, gemm_smem>>>(d_ah, d_al, d_bh, d_bl, d_qkv,
                                              MROWS, N_QKV, Cc);
    }

    // 3) causal flash attention (fp32)
    {
        dim3 grid(Tt / AQ, Bb * Hh);
        attn_kernel<<<grid, 128, attn_smem>>>(d_qkv, d_y);
    }

    // 4) split y and Wproj, then projection GEMM -> out
    {
        int n4 = MROWS * Cc / 4;
        split_kernel<<<(n4 + 255) / 256, 256>>>(d_y, d_ah, d_al, n4);
        int w4 = Cc * Cc / 4;
        split_kernel<<<(w4 + 255) / 256, 256>>>(Wproj, d_bh, d_bl, w4);
        dim3 grid(Cc / GBN, MROWS / GBM);
        gemm_bf16x3<<<grid, 256, gemm_smem>>>(d_ah, d_al, d_bh, d_bl, out,
                                              MROWS, Cc, Cc);
    }
}

// round 4
// speedup vs baseline: 2.8891x; 2.0681x over previous
#include <cuda_runtime.h>
#include <cuda_bf16.h>
#include <math.h>
#include <stdint.h>

// Problem constants
#define Bb 4
#define Tt 2048
#define Cc 1024
#define Hh 16
#define Dd 64
#define MROWS (Bb*Tt)          // 8192
#define N_QKV (3*Cc)           // 3072

// Scratch (__device__ globals: allocation-free rule)
__device__ float g_qkv[(size_t)MROWS * N_QKV];          // 100.7 MB fp32 qkv
__device__ float g_y[(size_t)MROWS * Cc];               // 33.5 MB
__device__ __nv_bfloat16 g_ah[(size_t)MROWS * Cc];      // split A hi
__device__ __nv_bfloat16 g_al[(size_t)MROWS * Cc];      // split A lo
__device__ __nv_bfloat16 g_bh[(size_t)Cc * N_QKV];      // split B hi
__device__ __nv_bfloat16 g_bl[(size_t)Cc * N_QKV];      // split B lo
__device__ __nv_bfloat16 g_qh[(size_t)MROWS * N_QKV];   // split qkv hi
__device__ __nv_bfloat16 g_ql[(size_t)MROWS * N_QKV];   // split qkv lo

// ---------------------------------------------------------------------------
// fp32 -> bf16 hi/lo split (elementwise, float4 vectorized)
// ---------------------------------------------------------------------------
__global__ __launch_bounds__(256) void split_kernel(
    const float* __restrict__ in,
    __nv_bfloat16* __restrict__ hi, __nv_bfloat16* __restrict__ lo, int n4)
{
    int i = blockIdx.x * blockDim.x + threadIdx.x;
    if (i >= n4) return;
    float4 v = ((const float4*)in)[i];
    float vv[4] = {v.x, v.y, v.z, v.w};
    __nv_bfloat16 h[4], l[4];
#pragma unroll
    for (int j = 0; j < 4; j++) {
        h[j] = __float2bfloat16(vv[j]);
        l[j] = __float2bfloat16(vv[j] - __bfloat162float(h[j]));
    }
    ((uint2*)hi)[i] = *(uint2*)h;
    ((uint2*)lo)[i] = *(uint2*)l;
}

// ---------------------------------------------------------------------------
// MMA / ldmatrix primitives
// ---------------------------------------------------------------------------
__device__ __forceinline__ void cp16(void* s, const void* g) {
    uint32_t sa = (uint32_t)__cvta_generic_to_shared(s);
    asm volatile("cp.async.cg.shared.global [%0], [%1], 16;" :: "r"(sa), "l"(g));
}
__device__ __forceinline__ void ldsm4(uint32_t* r, const __nv_bfloat16* p) {
    uint32_t a = (uint32_t)__cvta_generic_to_shared(p);
    asm volatile("ldmatrix.sync.aligned.m8n8.x4.shared.b16 {%0,%1,%2,%3}, [%4];"
        : "=r"(r[0]), "=r"(r[1]), "=r"(r[2]), "=r"(r[3]) : "r"(a));
}
__device__ __forceinline__ void ldsm2(uint32_t* r, const __nv_bfloat16* p) {
    uint32_t a = (uint32_t)__cvta_generic_to_shared(p);
    asm volatile("ldmatrix.sync.aligned.m8n8.x2.shared.b16 {%0,%1}, [%2];"
        : "=r"(r[0]), "=r"(r[1]) : "r"(a));
}
__device__ __forceinline__ void ldsm2t(uint32_t* r, const __nv_bfloat16* p) {
    uint32_t a = (uint32_t)__cvta_generic_to_shared(p);
    asm volatile("ldmatrix.sync.aligned.m8n8.x2.trans.shared.b16 {%0,%1}, [%2];"
        : "=r"(r[0]), "=r"(r[1]) : "r"(a));
}
__device__ __forceinline__ void mma16816(float* c, const uint32_t* a, const uint32_t* b) {
    asm volatile("mma.sync.aligned.m16n8k16.row.col.f32.bf16.bf16.f32 "
        "{%0,%1,%2,%3}, {%4,%5,%6,%7}, {%8,%9}, {%0,%1,%2,%3};"
        : "+f"(c[0]), "+f"(c[1]), "+f"(c[2]), "+f"(c[3])
        : "r"(a[0]), "r"(a[1]), "r"(a[2]), "r"(a[3]), "r"(b[0]), "r"(b[1]));
}
__device__ __forceinline__ void splitpack(float a, float b, uint32_t& h, uint32_t& l) {
    __nv_bfloat16 ha = __float2bfloat16_rn(a), hb = __float2bfloat16_rn(b);
    float la = a - __bfloat162float(ha), lb = b - __bfloat162float(hb);
    __nv_bfloat162 hh; hh.x = ha; hh.y = hb;
    __nv_bfloat162 ll = __floats2bfloat162_rn(la, lb);
    h = *(uint32_t*)&hh;
    l = *(uint32_t*)&ll;
}

// ---------------------------------------------------------------------------
// bf16x3 split GEMM (unchanged, proven): C = Ah@Bh + Ah@Bl + Al@Bh
// ---------------------------------------------------------------------------
#define GBM 128
#define GBN 128
#define GBK 32
#define ASTR 40
#define BSTR 136
#define SA_SZ (GBM*ASTR)
#define SB_SZ (GBK*BSTR)

__global__ __launch_bounds__(256) void gemm_bf16x3(
    const __nv_bfloat16* __restrict__ Ah, const __nv_bfloat16* __restrict__ Al,
    const __nv_bfloat16* __restrict__ Bh, const __nv_bfloat16* __restrict__ Bl,
    float* __restrict__ C, int M, int N, int K)
{
    extern __shared__ __nv_bfloat16 smraw[];
    __nv_bfloat16* sAh = smraw;
    __nv_bfloat16* sAl = smraw + 2 * SA_SZ;
    __nv_bfloat16* sBh = smraw + 4 * SA_SZ;
    __nv_bfloat16* sBl = smraw + 4 * SA_SZ + 2 * SB_SZ;

    const int tid  = threadIdx.x;
    const int bm   = blockIdx.y * GBM;
    const int bn   = blockIdx.x * GBN;
    const int lane = tid & 31;
    const int warp = tid >> 5;
    const int wm   = (warp & 1) * 64;
    const int wn   = (warp >> 1) * 32;

    const int ar = tid >> 1, aq = tid & 1;
    const int br = tid >> 3, bq = tid & 7;

    float acc[4][4][4];
#pragma unroll
    for (int i = 0; i < 4; i++)
#pragma unroll
        for (int j = 0; j < 4; j++)
#pragma unroll
            for (int t = 0; t < 4; t++) acc[i][j][t] = 0.f;

    const int nkt = K / GBK;

#define LOAD_TILE(K0, S)                                                         \
    {                                                                            \
        const size_t ga = (size_t)(bm + ar) * K + (K0) + aq * 16;                \
        __nv_bfloat16* dAh = sAh + (S) * SA_SZ + ar * ASTR + aq * 16;            \
        __nv_bfloat16* dAl = sAl + (S) * SA_SZ + ar * ASTR + aq * 16;            \
        cp16(dAh,     Ah + ga);                                                  \
        cp16(dAh + 8, Ah + ga + 8);                                              \
        cp16(dAl,     Al + ga);                                                  \
        cp16(dAl + 8, Al + ga + 8);                                              \
        const size_t gb = (size_t)((K0) + br) * N + bn + bq * 16;                \
        __nv_bfloat16* dBh = sBh + (S) * SB_SZ + br * BSTR + bq * 16;            \
        __nv_bfloat16* dBl = sBl + (S) * SB_SZ + br * BSTR + bq * 16;            \
        cp16(dBh,     Bh + gb);                                                  \
        cp16(dBh + 8, Bh + gb + 8);                                              \
        cp16(dBl,     Bl + gb);                                                  \
        cp16(dBl + 8, Bl + gb + 8);                                              \
    }

    LOAD_TILE(0, 0);
    asm volatile("cp.async.commit_group;");

    for (int kt = 0; kt < nkt; kt++) {
        const int cur = kt & 1;
        const bool has_next = (kt + 1 < nkt);
        if (has_next) {
            LOAD_TILE((kt + 1) * GBK, cur ^ 1);
            asm volatile("cp.async.commit_group;");
            asm volatile("cp.async.wait_group 1;");
        } else {
            asm volatile("cp.async.wait_group 0;");
        }
        __syncthreads();

        const __nv_bfloat16* pAh = sAh + cur * SA_SZ;
        const __nv_bfloat16* pAl = sAl + cur * SA_SZ;
        const __nv_bfloat16* pBh = sBh + cur * SB_SZ;
        const __nv_bfloat16* pBl = sBl + cur * SB_SZ;

#pragma unroll
        for (int ks = 0; ks < 2; ks++) {
            uint32_t afh[4][4], afl[4][4], bfh[4][2], bfl[4][2];
            const int arow = lane & 15;
            const int acol = ks * 16 + (lane >> 4) * 8;
#pragma unroll
            for (int mt = 0; mt < 4; mt++) {
                const int off = (wm + mt * 16 + arow) * ASTR + acol;
                ldsm4(afh[mt], pAh + off);
                ldsm4(afl[mt], pAl + off);
            }
            const int brow = ks * 16 + (lane & 15);
#pragma unroll
            for (int nt = 0; nt < 4; nt++) {
                const int off = brow * BSTR + wn + nt * 8;
                ldsm2t(bfh[nt], pBh + off);
                ldsm2t(bfl[nt], pBl + off);
            }
#pragma unroll
            for (int mt = 0; mt < 4; mt++)
#pragma unroll
                for (int nt = 0; nt < 4; nt++) {
                    mma16816(acc[mt][nt], afh[mt], bfh[nt]);
                    mma16816(acc[mt][nt], afh[mt], bfl[nt]);
                    mma16816(acc[mt][nt], afl[mt], bfh[nt]);
                }
        }
        __syncthreads();
    }

#pragma unroll
    for (int mt = 0; mt < 4; mt++) {
        const int row = bm + wm + mt * 16 + (lane >> 2);
#pragma unroll
        for (int nt = 0; nt < 4; nt++) {
            const int col = bn + wn + nt * 8 + (lane & 3) * 2;
            *(float2*)&C[(size_t)row * N + col] =
                make_float2(acc[mt][nt][0], acc[mt][nt][1]);
            *(float2*)&C[(size_t)(row + 8) * N + col] =
                make_float2(acc[mt][nt][2], acc[mt][nt][3]);
        }
    }
#undef LOAD_TILE
}

// ---------------------------------------------------------------------------
// Tensor-core causal flash attention, bf16 hi/lo split everywhere.
// Block: 128 threads (4 warps), 64 q rows/block (16 per warp), 64-key tiles.
// Smem: double-buffered [Kh|Kl|Vh|Vl] tiles, each 64 x 72 bf16.
// ---------------------------------------------------------------------------
#define KSTR 72
#define SMTILE (64*KSTR)       // one array
#define SMBUF  (4*SMTILE)      // one buffer (Kh,Kl,Vh,Vl)

__global__ __launch_bounds__(128) void attn_mma(
    const __nv_bfloat16* __restrict__ qh, const __nv_bfloat16* __restrict__ ql,
    float* __restrict__ y)
{
    extern __shared__ __nv_bfloat16 sm[];

    const int tid  = threadIdx.x;
    const int lane = tid & 31;
    const int warp = tid >> 5;
    const int l16  = lane & 15;
    const int qt   = blockIdx.x;
    const int bh   = blockIdx.y;
    const int b    = bh >> 4;
    const int h    = bh & 15;
    const int qb   = qt * 64;

    const int srow = tid >> 1;           // staging row 0..63
    const int sdb  = (tid & 1) * 32;     // staging col base

    // ---- stage Q tile (buffer 0: Kh/Kl slots), load Q fragments ----
    {
        const size_t gq = (size_t)(b * Tt + qb + srow) * N_QKV + h * Dd + sdb;
        __nv_bfloat16* dQh = sm + srow * KSTR + sdb;
        __nv_bfloat16* dQl = sm + SMTILE + srow * KSTR + sdb;
#pragma unroll
        for (int c = 0; c < 32; c += 8) {
            cp16(dQh + c, qh + gq + c);
            cp16(dQl + c, ql + gq + c);
        }
        asm volatile("cp.async.commit_group;");
        asm volatile("cp.async.wait_group 0;");
        __syncthreads();
    }

    uint32_t Qhf[4][4], Qlf[4][4];
#pragma unroll
    for (int ks = 0; ks < 4; ks++) {
        const int off = (warp * 16 + l16) * KSTR + ks * 16 + ((lane >> 4) << 3);
        ldsm4(Qhf[ks], sm + off);
        ldsm4(Qlf[ks], sm + SMTILE + off);
    }
    __syncthreads();   // frags in regs; buffer 0 may be overwritten

    float o[8][4];
#pragma unroll
    for (int nt = 0; nt < 8; nt++)
#pragma unroll
        for (int e = 0; e < 4; e++) o[nt][e] = 0.f;
    float m0 = -1e30f, m1 = -1e30f, l0 = 0.f, l1 = 0.f;

    const int rl0 = warp * 16 + (lane >> 2);  // local q row (and +8)

#define STAGE_KV(Sb, KB)                                                          \
    {                                                                             \
        const size_t gk = (size_t)(b * Tt + (KB) + srow) * N_QKV + h * Dd + sdb;  \
        __nv_bfloat16* base = sm + (Sb) * SMBUF + srow * KSTR + sdb;              \
        _Pragma("unroll")                                                         \
        for (int c = 0; c < 32; c += 8) {                                         \
            cp16(base + c,              qh + gk + Cc + c);                        \
            cp16(base + SMTILE + c,     ql + gk + Cc + c);                        \
            cp16(base + 2*SMTILE + c,   qh + gk + 2*Cc + c);                      \
            cp16(base + 3*SMTILE + c,   ql + gk + 2*Cc + c);                      \
        }                                                                         \
    }

    STAGE_KV(0, 0);
    asm volatile("cp.async.commit_group;");

    for (int kt = 0; kt <= qt; kt++) {
        const int cur = kt & 1;
        if (kt < qt) {
            STAGE_KV(cur ^ 1, (kt + 1) * 64);
            asm volatile("cp.async.commit_group;");
            asm volatile("cp.async.wait_group 1;");
        } else {
            asm volatile("cp.async.wait_group 0;");
        }
        __syncthreads();

        const __nv_bfloat16* pKh = sm + cur * SMBUF;
        const __nv_bfloat16* pKl = pKh + SMTILE;
        const __nv_bfloat16* pVh = pKh + 2 * SMTILE;
        const __nv_bfloat16* pVl = pKh + 3 * SMTILE;

        // ---- S = Q @ K^T (3-way split) ----
        float s[8][4];
#pragma unroll
        for (int nt = 0; nt < 8; nt++)
#pragma unroll
            for (int e = 0; e < 4; e++) s[nt][e] = 0.f;

#pragma unroll
        for (int ks = 0; ks < 4; ks++) {
#pragma unroll
            for (int nt = 0; nt < 8; nt++) {
                const int off = (nt * 8 + (l16 & 7)) * KSTR + ks * 16 + ((l16 >> 3) << 3);
                uint32_t kbh[2], kbl[2];
                ldsm2(kbh, pKh + off);
                ldsm2(kbl, pKl + off);
                mma16816(s[nt], Qhf[ks], kbh);
                mma16816(s[nt], Qhf[ks], kbl);
                mma16816(s[nt], Qlf[ks], kbh);
            }
        }

        // ---- scale + causal mask ----
#pragma unroll
        for (int nt = 0; nt < 8; nt++)
#pragma unroll
            for (int e = 0; e < 4; e++) s[nt][e] *= 0.125f;

        if (kt == qt) {
#pragma unroll
            for (int nt = 0; nt < 8; nt++) {
                const int cl = nt * 8 + ((lane & 3) << 1);
                if (cl     > rl0)     s[nt][0] = -1e30f;
                if (cl + 1 > rl0)     s[nt][1] = -1e30f;
                if (cl     > rl0 + 8) s[nt][2] = -1e30f;
                if (cl + 1 > rl0 + 8) s[nt][3] = -1e30f;
            }
        }

        // ---- online softmax ----
        float mt0 = -1e30f, mt1 = -1e30f;
#pragma unroll
        for (int nt = 0; nt < 8; nt++) {
            mt0 = fmaxf(mt0, fmaxf(s[nt][0], s[nt][1]));
            mt1 = fmaxf(mt1, fmaxf(s[nt][2], s[nt][3]));
        }
        mt0 = fmaxf(mt0, __shfl_xor_sync(0xffffffff, mt0, 1));
        mt0 = fmaxf(mt0, __shfl_xor_sync(0xffffffff, mt0, 2));
        mt1 = fmaxf(mt1, __shfl_xor_sync(0xffffffff, mt1, 1));
        mt1 = fmaxf(mt1, __shfl_xor_sync(0xffffffff, mt1, 2));

        const float mn0 = fmaxf(m0, mt0);
        const float mn1 = fmaxf(m1, mt1);
        const float f0 = __expf(m0 - mn0);
        const float f1 = __expf(m1 - mn1);
        m0 = mn0; m1 = mn1;
        l0 *= f0; l1 *= f1;
#pragma unroll
        for (int nt = 0; nt < 8; nt++) {
            o[nt][0] *= f0; o[nt][1] *= f0;
            o[nt][2] *= f1; o[nt][3] *= f1;
        }

        // ---- P = exp(S - m), split hi/lo, repack as A fragments ----
        uint32_t Ahf[4][4], Alf[4][4];
#pragma unroll
        for (int kc = 0; kc < 4; kc++) {
            const int t0 = 2 * kc, t1 = 2 * kc + 1;
            float p00 = __expf(s[t0][0] - m0), p01 = __expf(s[t0][1] - m0);
            float p02 = __expf(s[t0][2] - m1), p03 = __expf(s[t0][3] - m1);
            float p10 = __expf(s[t1][0] - m0), p11 = __expf(s[t1][1] - m0);
            float p12 = __expf(s[t1][2] - m1), p13 = __expf(s[t1][3] - m1);
            l0 += (p00 + p01) + (p10 + p11);
            l1 += (p02 + p03) + (p12 + p13);
            splitpack(p00, p01, Ahf[kc][0], Alf[kc][0]);
            splitpack(p02, p03, Ahf[kc][1], Alf[kc][1]);
            splitpack(p10, p11, Ahf[kc][2], Alf[kc][2]);
            splitpack(p12, p13, Ahf[kc][3], Alf[kc][3]);
        }

        // ---- O += P @ V (3-way split) ----
#pragma unroll
        for (int nt = 0; nt < 8; nt++) {
#pragma unroll
            for (int kc = 0; kc < 4; kc++) {
                const int off = (kc * 16 + l16) * KSTR + nt * 8;
                uint32_t vbh[2], vbl[2];
                ldsm2t(vbh, pVh + off);
                ldsm2t(vbl, pVl + off);
                mma16816(o[nt], Ahf[kc], vbh);
                mma16816(o[nt], Ahf[kc], vbl);
                mma16816(o[nt], Alf[kc], vbh);
            }
        }
        __syncthreads();   // reads of cur done before next stage overwrites
    }

    // ---- finalize: reduce l across the 4-lane row group, divide, store ----
    l0 += __shfl_xor_sync(0xffffffff, l0, 1);
    l0 += __shfl_xor_sync(0xffffffff, l0, 2);
    l1 += __shfl_xor_sync(0xffffffff, l1, 1);
    l1 += __shfl_xor_sync(0xffffffff, l1, 2);
    const float inv0 = 1.f / l0;
    const float inv1 = 1.f / l1;

    const int r0 = qb + warp * 16 + (lane >> 2);
    const int c0 = h * Dd + ((lane & 3) << 1);
#pragma unroll
    for (int nt = 0; nt < 8; nt++) {
        *(float2*)&y[(size_t)(b * Tt + r0) * Cc + c0 + nt * 8] =
            make_float2(o[nt][0] * inv0, o[nt][1] * inv0);
        *(float2*)&y[(size_t)(b * Tt + r0 + 8) * Cc + c0 + nt * 8] =
            make_float2(o[nt][2] * inv1, o[nt][3] * inv1);
    }
#undef STAGE_KV
}

// ---------------------------------------------------------------------------
// Launch
// ---------------------------------------------------------------------------
extern "C" void kernel_launch(void* const* d_in, const int* in_sizes, int n_in,
                              void* d_out, int out_size)
{
    const float* x     = (const float*)d_in[0];
    const float* Wqkv  = (const float*)d_in[1];
    const float* Wproj = (const float*)d_in[2];
    float* out = (float*)d_out;

    const int gemm_smem = (4 * SA_SZ + 4 * SB_SZ) * sizeof(__nv_bfloat16);
    const int attn_smem = 2 * SMBUF * sizeof(__nv_bfloat16);   // 73728
    cudaFuncSetAttribute(gemm_bf16x3, cudaFuncAttributeMaxDynamicSharedMemorySize, gemm_smem);
    cudaFuncSetAttribute(attn_mma,   cudaFuncAttributeMaxDynamicSharedMemorySize, attn_smem);

    float *d_qkv, *d_y;
    __nv_bfloat16 *d_ah, *d_al, *d_bh, *d_bl, *d_qh, *d_ql;
    cudaGetSymbolAddress((void**)&d_qkv, g_qkv);
    cudaGetSymbolAddress((void**)&d_y, g_y);
    cudaGetSymbolAddress((void**)&d_ah, g_ah);
    cudaGetSymbolAddress((void**)&d_al, g_al);
    cudaGetSymbolAddress((void**)&d_bh, g_bh);
    cudaGetSymbolAddress((void**)&d_bl, g_bl);
    cudaGetSymbolAddress((void**)&d_qh, g_qh);
    cudaGetSymbolAddress((void**)&d_ql, g_ql);

    // 1) split x, Wqkv
    {
        int n4 = MROWS * Cc / 4;
        split_kernel<<<(n4 + 255) / 256, 256>>>(x, d_ah, d_al, n4);
        int w4 = Cc * N_QKV / 4;
        split_kernel<<<(w4 + 255) / 256, 256>>>(Wqkv, d_bh, d_bl, w4);
    }
    // 2) QKV GEMM -> fp32 qkv
    {
        dim3 grid(N_QKV / GBN, MROWS / GBM);
        gemm_bf16x3<<<grid, 256, gemm_smem>>>(d_ah, d_al, d_bh, d_bl, d_qkv,
                                              MROWS, N_QKV, Cc);
    }
    // 3) split qkv -> bf16 hi/lo
    {
        int n4 = MROWS * N_QKV / 4;
        split_kernel<<<(n4 + 255) / 256, 256>>>(d_qkv, d_qh, d_ql, n4);
    }
    // 4) tensor-core causal attention
    {
        dim3 grid(Tt / 64, Bb * Hh);
        attn_mma<<<grid, 128, attn_smem>>>(d_qh, d_ql, d_y);
    }
    // 5) split y, Wproj; projection GEMM
    {
        int n4 = MROWS * Cc / 4;
        split_kernel<<<(n4 + 255) / 256, 256>>>(d_y, d_ah, d_al, n4);
        int w4 = Cc * Cc / 4;
        split_kernel<<<(w4 + 255) / 256, 256>>>(Wproj, d_bh, d_bl, w4);
        dim3 grid(Cc / GBN, MROWS / GBM);
        gemm_bf16x3<<<grid, 256, gemm_smem>>>(d_ah, d_al, d_bh, d_bl, out,
                                              MROWS, Cc, Cc);
    }
}

// round 9
// speedup vs baseline: 2.8961x; 1.0024x over previous
#include <cuda_runtime.h>
#include <cuda_bf16.h>
#include <math.h>
#include <stdint.h>

// Problem constants
#define Bb 4
#define Tt 2048
#define Cc 1024
#define Hh 16
#define Dd 64
#define MROWS (Bb*Tt)          // 8192
#define N_QKV (3*Cc)           // 3072

// Scratch (__device__ globals: allocation-free rule)
__device__ __nv_bfloat16 g_ah[(size_t)MROWS * Cc];      // A hi (x, then y)
__device__ __nv_bfloat16 g_al[(size_t)MROWS * Cc];      // A lo
__device__ __nv_bfloat16 g_bh[(size_t)Cc * N_QKV];      // B hi (Wqkv, then Wproj)
__device__ __nv_bfloat16 g_bl[(size_t)Cc * N_QKV];      // B lo
__device__ __nv_bfloat16 g_qh[(size_t)MROWS * N_QKV];   // qkv hi
__device__ __nv_bfloat16 g_ql[(size_t)MROWS * N_QKV];   // qkv lo

// ---------------------------------------------------------------------------
// fp32 -> bf16 hi/lo split (elementwise)
// ---------------------------------------------------------------------------
__global__ __launch_bounds__(256) void split_kernel(
    const float* __restrict__ in,
    __nv_bfloat16* __restrict__ hi, __nv_bfloat16* __restrict__ lo, int n4)
{
    int i = blockIdx.x * blockDim.x + threadIdx.x;
    if (i >= n4) return;
    float4 v = ((const float4*)in)[i];
    float vv[4] = {v.x, v.y, v.z, v.w};
    __nv_bfloat16 h[4], l[4];
#pragma unroll
    for (int j = 0; j < 4; j++) {
        h[j] = __float2bfloat16(vv[j]);
        l[j] = __float2bfloat16(vv[j] - __bfloat162float(h[j]));
    }
    ((uint2*)hi)[i] = *(uint2*)h;
    ((uint2*)lo)[i] = *(uint2*)l;
}

// ---------------------------------------------------------------------------
// primitives
// ---------------------------------------------------------------------------
__device__ __forceinline__ void cp16(void* s, const void* g) {
    uint32_t sa = (uint32_t)__cvta_generic_to_shared(s);
    asm volatile("cp.async.cg.shared.global [%0], [%1], 16;" :: "r"(sa), "l"(g));
}
__device__ __forceinline__ void ldsm4(uint32_t* r, const __nv_bfloat16* p) {
    uint32_t a = (uint32_t)__cvta_generic_to_shared(p);
    asm volatile("ldmatrix.sync.aligned.m8n8.x4.shared.b16 {%0,%1,%2,%3}, [%4];"
        : "=r"(r[0]), "=r"(r[1]), "=r"(r[2]), "=r"(r[3]) : "r"(a));
}
__device__ __forceinline__ void ldsm2(uint32_t* r, const __nv_bfloat16* p) {
    uint32_t a = (uint32_t)__cvta_generic_to_shared(p);
    asm volatile("ldmatrix.sync.aligned.m8n8.x2.shared.b16 {%0,%1}, [%2];"
        : "=r"(r[0]), "=r"(r[1]) : "r"(a));
}
__device__ __forceinline__ void ldsm2t(uint32_t* r, const __nv_bfloat16* p) {
    uint32_t a = (uint32_t)__cvta_generic_to_shared(p);
    asm volatile("ldmatrix.sync.aligned.m8n8.x2.trans.shared.b16 {%0,%1}, [%2];"
        : "=r"(r[0]), "=r"(r[1]) : "r"(a));
}
__device__ __forceinline__ void mma16816(float* c, const uint32_t* a, const uint32_t* b) {
    asm volatile("mma.sync.aligned.m16n8k16.row.col.f32.bf16.bf16.f32 "
        "{%0,%1,%2,%3}, {%4,%5,%6,%7}, {%8,%9}, {%0,%1,%2,%3};"
        : "+f"(c[0]), "+f"(c[1]), "+f"(c[2]), "+f"(c[3])
        : "r"(a[0]), "r"(a[1]), "r"(a[2]), "r"(a[3]), "r"(b[0]), "r"(b[1]));
}
__device__ __forceinline__ void splitpack(float a, float b, uint32_t& h, uint32_t& l) {
    __nv_bfloat16 ha = __float2bfloat16_rn(a), hb = __float2bfloat16_rn(b);
    float la = a - __bfloat162float(ha), lb = b - __bfloat162float(hb);
    __nv_bfloat162 hh; hh.x = ha; hh.y = hb;
    __nv_bfloat162 ll = __floats2bfloat162_rn(la, lb);
    h = *(uint32_t*)&hh;
    l = *(uint32_t*)&ll;
}
// fast 2^t on fma/alu pipes (t <= 0; clamped at -126). err ~4e-5 rel.
__device__ __forceinline__ float exp2a(float t) {
    t = fmaxf(t, -126.0f);
    float r = t + 12582912.0f;               // round-to-nearest-int magic
    float f = t - (r - 12582912.0f);         // f in [-0.5, 0.5]
    float p = fmaf(0.0096181f, f, 0.0555041f);
    p = fmaf(p, f, 0.2402265f);
    p = fmaf(p, f, 0.6931472f);
    p = fmaf(p, f, 1.0f);
    return __int_as_float(__float_as_int(p) + (__float_as_int(r) << 23));
}

// ---------------------------------------------------------------------------
// bf16x3 split GEMM: C = Ah@Bh + Ah@Bl + Al@Bh (fp32 acc).
// SPLIT_OUT: write hi/lo bf16 instead of fp32.
// ---------------------------------------------------------------------------
#define GBM 128
#define GBN 128
#define GBK 32
#define ASTR 40
#define BSTR 136
#define SA_SZ (GBM*ASTR)
#define SB_SZ (GBK*BSTR)

template<bool SPLIT_OUT>
__global__ __launch_bounds__(256) void gemm_bf16x3(
    const __nv_bfloat16* __restrict__ Ah, const __nv_bfloat16* __restrict__ Al,
    const __nv_bfloat16* __restrict__ Bh, const __nv_bfloat16* __restrict__ Bl,
    float* __restrict__ Cf,
    __nv_bfloat16* __restrict__ Ch, __nv_bfloat16* __restrict__ Cl,
    int M, int N, int K)
{
    extern __shared__ __nv_bfloat16 smraw[];
    __nv_bfloat16* sAh = smraw;
    __nv_bfloat16* sAl = smraw + 2 * SA_SZ;
    __nv_bfloat16* sBh = smraw + 4 * SA_SZ;
    __nv_bfloat16* sBl = smraw + 4 * SA_SZ + 2 * SB_SZ;

    const int tid  = threadIdx.x;
    const int bm   = blockIdx.y * GBM;
    const int bn   = blockIdx.x * GBN;
    const int lane = tid & 31;
    const int warp = tid >> 5;
    const int wm   = (warp & 1) * 64;
    const int wn   = (warp >> 1) * 32;

    const int ar = tid >> 1, aq = tid & 1;
    const int br = tid >> 3, bq = tid & 7;

    float acc[4][4][4];
#pragma unroll
    for (int i = 0; i < 4; i++)
#pragma unroll
        for (int j = 0; j < 4; j++)
#pragma unroll
            for (int t = 0; t < 4; t++) acc[i][j][t] = 0.f;

    const int nkt = K / GBK;

#define LOAD_TILE(K0, S)                                                         \
    {                                                                            \
        const size_t ga = (size_t)(bm + ar) * K + (K0) + aq * 16;                \
        __nv_bfloat16* dAh = sAh + (S) * SA_SZ + ar * ASTR + aq * 16;            \
        __nv_bfloat16* dAl = sAl + (S) * SA_SZ + ar * ASTR + aq * 16;            \
        cp16(dAh,     Ah + ga);                                                  \
        cp16(dAh + 8, Ah + ga + 8);                                              \
        cp16(dAl,     Al + ga);                                                  \
        cp16(dAl + 8, Al + ga + 8);                                              \
        const size_t gb = (size_t)((K0) + br) * N + bn + bq * 16;                \
        __nv_bfloat16* dBh = sBh + (S) * SB_SZ + br * BSTR + bq * 16;            \
        __nv_bfloat16* dBl = sBl + (S) * SB_SZ + br * BSTR + bq * 16;            \
        cp16(dBh,     Bh + gb);                                                  \
        cp16(dBh + 8, Bh + gb + 8);                                              \
        cp16(dBl,     Bl + gb);                                                  \
        cp16(dBl + 8, Bl + gb + 8);                                              \
    }

    LOAD_TILE(0, 0);
    asm volatile("cp.async.commit_group;");

    for (int kt = 0; kt < nkt; kt++) {
        const int cur = kt & 1;
        if (kt + 1 < nkt) {
            LOAD_TILE((kt + 1) * GBK, cur ^ 1);
            asm volatile("cp.async.commit_group;");
            asm volatile("cp.async.wait_group 1;");
        } else {
            asm volatile("cp.async.wait_group 0;");
        }
        __syncthreads();

        const __nv_bfloat16* pAh = sAh + cur * SA_SZ;
        const __nv_bfloat16* pAl = sAl + cur * SA_SZ;
        const __nv_bfloat16* pBh = sBh + cur * SB_SZ;
        const __nv_bfloat16* pBl = sBl + cur * SB_SZ;

#pragma unroll
        for (int ks = 0; ks < 2; ks++) {
            uint32_t afh[4][4], afl[4][4], bfh[4][2], bfl[4][2];
            const int arow = lane & 15;
            const int acol = ks * 16 + (lane >> 4) * 8;
#pragma unroll
            for (int mt = 0; mt < 4; mt++) {
                const int off = (wm + mt * 16 + arow) * ASTR + acol;
                ldsm4(afh[mt], pAh + off);
                ldsm4(afl[mt], pAl + off);
            }
            const int brow = ks * 16 + (lane & 15);
#pragma unroll
            for (int nt = 0; nt < 4; nt++) {
                const int off = brow * BSTR + wn + nt * 8;
                ldsm2t(bfh[nt], pBh + off);
                ldsm2t(bfl[nt], pBl + off);
            }
#pragma unroll
            for (int mt = 0; mt < 4; mt++)
#pragma unroll
                for (int nt = 0; nt < 4; nt++) {
                    mma16816(acc[mt][nt], afh[mt], bfh[nt]);
                    mma16816(acc[mt][nt], afh[mt], bfl[nt]);
                    mma16816(acc[mt][nt], afl[mt], bfh[nt]);
                }
        }
        __syncthreads();
    }

#pragma unroll
    for (int mt = 0; mt < 4; mt++) {
        const int row = bm + wm + mt * 16 + (lane >> 2);
#pragma unroll
        for (int nt = 0; nt < 4; nt++) {
            const int col = bn + wn + nt * 8 + (lane & 3) * 2;
            if (SPLIT_OUT) {
                uint32_t h0, l0v, h1, l1v;
                splitpack(acc[mt][nt][0], acc[mt][nt][1], h0, l0v);
                splitpack(acc[mt][nt][2], acc[mt][nt][3], h1, l1v);
                *(uint32_t*)&Ch[(size_t)row * N + col] = h0;
                *(uint32_t*)&Cl[(size_t)row * N + col] = l0v;
                *(uint32_t*)&Ch[(size_t)(row + 8) * N + col] = h1;
                *(uint32_t*)&Cl[(size_t)(row + 8) * N + col] = l1v;
            } else {
                *(float2*)&Cf[(size_t)row * N + col] =
                    make_float2(acc[mt][nt][0], acc[mt][nt][1]);
                *(float2*)&Cf[(size_t)(row + 8) * N + col] =
                    make_float2(acc[mt][nt][2], acc[mt][nt][3]);
            }
        }
    }
#undef LOAD_TILE
}

// ---------------------------------------------------------------------------
// Tensor-core causal flash attention.
// QK^T: 3-way hi/lo split. P: hi/lo split (3-way PV). V: hi/lo split.
// Softmax in log2 domain with FMA-pipe exp2. Output pre-split (hi/lo bf16).
// ---------------------------------------------------------------------------
#define KSTR 72
#define SMTILE (64*KSTR)
#define SMBUF  (4*SMTILE)
#define SCALE2 0.1803368801111191f   /* 0.125 * log2(e) */

__global__ __launch_bounds__(128) void attn_mma(
    const __nv_bfloat16* __restrict__ qh, const __nv_bfloat16* __restrict__ ql,
    __nv_bfloat16* __restrict__ yh, __nv_bfloat16* __restrict__ yl)
{
    extern __shared__ __nv_bfloat16 sm[];

    const int tid  = threadIdx.x;
    const int lane = tid & 31;
    const int warp = tid >> 5;
    const int l16  = lane & 15;
    const int qt   = blockIdx.x;
    const int bh   = blockIdx.y;
    const int b    = bh >> 4;
    const int h    = bh & 15;
    const int qb   = qt * 64;

    const int srow = tid >> 1;
    const int sdb  = (tid & 1) * 32;

    // stage Q, load fragments
    {
        const size_t gq = (size_t)(b * Tt + qb + srow) * N_QKV + h * Dd + sdb;
        __nv_bfloat16* dQh = sm + srow * KSTR + sdb;
        __nv_bfloat16* dQl = sm + SMTILE + srow * KSTR + sdb;
#pragma unroll
        for (int c = 0; c < 32; c += 8) {
            cp16(dQh + c, qh + gq + c);
            cp16(dQl + c, ql + gq + c);
        }
        asm volatile("cp.async.commit_group;");
        asm volatile("cp.async.wait_group 0;");
        __syncthreads();
    }

    uint32_t Qhf[4][4], Qlf[4][4];
#pragma unroll
    for (int ks = 0; ks < 4; ks++) {
        const int off = (warp * 16 + l16) * KSTR + ks * 16 + ((lane >> 4) << 3);
        ldsm4(Qhf[ks], sm + off);
        ldsm4(Qlf[ks], sm + SMTILE + off);
    }
    __syncthreads();

    float o[8][4];
#pragma unroll
    for (int nt = 0; nt < 8; nt++)
#pragma unroll
        for (int e = 0; e < 4; e++) o[nt][e] = 0.f;
    float m0 = -1e30f, m1 = -1e30f, l0 = 0.f, l1 = 0.f;

    const int rl0 = warp * 16 + (lane >> 2);

#define STAGE_KV(Sb, KB)                                                          \
    {                                                                             \
        const size_t gk = (size_t)(b * Tt + (KB) + srow) * N_QKV + h * Dd + sdb;  \
        __nv_bfloat16* base = sm + (Sb) * SMBUF + srow * KSTR + sdb;              \
        _Pragma("unroll")                                                         \
        for (int c = 0; c < 32; c += 8) {                                         \
            cp16(base + c,              qh + gk + Cc + c);                        \
            cp16(base + SMTILE + c,     ql + gk + Cc + c);                        \
            cp16(base + 2*SMTILE + c,   qh + gk + 2*Cc + c);                      \
            cp16(base + 3*SMTILE + c,   ql + gk + 2*Cc + c);                      \
        }                                                                         \
    }

    STAGE_KV(0, 0);
    asm volatile("cp.async.commit_group;");

    for (int kt = 0; kt <= qt; kt++) {
        const int cur = kt & 1;
        if (kt < qt) {
            STAGE_KV(cur ^ 1, (kt + 1) * 64);
            asm volatile("cp.async.commit_group;");
            asm volatile("cp.async.wait_group 1;");
        } else {
            asm volatile("cp.async.wait_group 0;");
        }
        __syncthreads();

        const __nv_bfloat16* pKh = sm + cur * SMBUF;
        const __nv_bfloat16* pKl = pKh + SMTILE;
        const __nv_bfloat16* pVh = pKh + 2 * SMTILE;
        const __nv_bfloat16* pVl = pKh + 3 * SMTILE;

        // S = Q @ K^T (3-way split)
        float s[8][4];
#pragma unroll
        for (int nt = 0; nt < 8; nt++)
#pragma unroll
            for (int e = 0; e < 4; e++) s[nt][e] = 0.f;

#pragma unroll
        for (int ks = 0; ks < 4; ks++) {
#pragma unroll
            for (int nt = 0; nt < 8; nt++) {
                const int off = (nt * 8 + (l16 & 7)) * KSTR + ks * 16 + ((l16 >> 3) << 3);
                uint32_t kbh[2], kbl[2];
                ldsm2(kbh, pKh + off);
                ldsm2(kbl, pKl + off);
                mma16816(s[nt], Qhf[ks], kbh);
                mma16816(s[nt], Qhf[ks], kbl);
                mma16816(s[nt], Qlf[ks], kbh);
            }
        }

        // scale into log2 domain + causal mask
#pragma unroll
        for (int nt = 0; nt < 8; nt++)
#pragma unroll
            for (int e = 0; e < 4; e++) s[nt][e] *= SCALE2;

        if (kt == qt) {
#pragma unroll
            for (int nt = 0; nt < 8; nt++) {
                const int cl = nt * 8 + ((lane & 3) << 1);
                if (cl     > rl0)     s[nt][0] = -1e30f;
                if (cl + 1 > rl0)     s[nt][1] = -1e30f;
                if (cl     > rl0 + 8) s[nt][2] = -1e30f;
                if (cl + 1 > rl0 + 8) s[nt][3] = -1e30f;
            }
        }

        // online softmax (base-2)
        float mt0 = -1e30f, mt1 = -1e30f;
#pragma unroll
        for (int nt = 0; nt < 8; nt++) {
            mt0 = fmaxf(mt0, fmaxf(s[nt][0], s[nt][1]));
            mt1 = fmaxf(mt1, fmaxf(s[nt][2], s[nt][3]));
        }
        mt0 = fmaxf(mt0, __shfl_xor_sync(0xffffffff, mt0, 1));
        mt0 = fmaxf(mt0, __shfl_xor_sync(0xffffffff, mt0, 2));
        mt1 = fmaxf(mt1, __shfl_xor_sync(0xffffffff, mt1, 1));
        mt1 = fmaxf(mt1, __shfl_xor_sync(0xffffffff, mt1, 2));

        const float mn0 = fmaxf(m0, mt0);
        const float mn1 = fmaxf(m1, mt1);
        const float f0 = exp2a(m0 - mn0);
        const float f1 = exp2a(m1 - mn1);
        m0 = mn0; m1 = mn1;
        l0 *= f0; l1 *= f1;
#pragma unroll
        for (int nt = 0; nt < 8; nt++) {
            o[nt][0] *= f0; o[nt][1] *= f0;
            o[nt][2] *= f1; o[nt][3] *= f1;
        }

        // P = 2^(s-m), hi/lo split A fragments
        uint32_t Phf[4][4], Plf[4][4];
#pragma unroll
        for (int kc = 0; kc < 4; kc++) {
            const int t0 = 2 * kc, t1 = 2 * kc + 1;
            float p00 = exp2a(s[t0][0] - m0), p01 = exp2a(s[t0][1] - m0);
            float p02 = exp2a(s[t0][2] - m1), p03 = exp2a(s[t0][3] - m1);
            float p10 = exp2a(s[t1][0] - m0), p11 = exp2a(s[t1][1] - m0);
            float p12 = exp2a(s[t1][2] - m1), p13 = exp2a(s[t1][3] - m1);
            l0 += (p00 + p01) + (p10 + p11);
            l1 += (p02 + p03) + (p12 + p13);
            splitpack(p00, p01, Phf[kc][0], Plf[kc][0]);
            splitpack(p02, p03, Phf[kc][1], Plf[kc][1]);
            splitpack(p10, p11, Phf[kc][2], Plf[kc][2]);
            splitpack(p12, p13, Phf[kc][3], Plf[kc][3]);
        }

        // O += Ph@(Vh+Vl) + Pl@Vh
#pragma unroll
        for (int nt = 0; nt < 8; nt++) {
#pragma unroll
            for (int kc = 0; kc < 4; kc++) {
                const int off = (kc * 16 + l16) * KSTR + nt * 8;
                uint32_t vbh[2], vbl[2];
                ldsm2t(vbh, pVh + off);
                ldsm2t(vbl, pVl + off);
                mma16816(o[nt], Phf[kc], vbh);
                mma16816(o[nt], Phf[kc], vbl);
                mma16816(o[nt], Plf[kc], vbh);
            }
        }
        __syncthreads();
    }

    // finalize
    l0 += __shfl_xor_sync(0xffffffff, l0, 1);
    l0 += __shfl_xor_sync(0xffffffff, l0, 2);
    l1 += __shfl_xor_sync(0xffffffff, l1, 1);
    l1 += __shfl_xor_sync(0xffffffff, l1, 2);
    const float inv0 = 1.f / l0;
    const float inv1 = 1.f / l1;

    const int r0 = qb + warp * 16 + (lane >> 2);
    const int c0 = h * Dd + ((lane & 3) << 1);
#pragma unroll
    for (int nt = 0; nt < 8; nt++) {
        uint32_t h0, l0v, h1, l1v;
        splitpack(o[nt][0] * inv0, o[nt][1] * inv0, h0, l0v);
        splitpack(o[nt][2] * inv1, o[nt][3] * inv1, h1, l1v);
        const size_t i0 = (size_t)(b * Tt + r0) * Cc + c0 + nt * 8;
        const size_t i1 = (size_t)(b * Tt + r0 + 8) * Cc + c0 + nt * 8;
        *(uint32_t*)&yh[i0] = h0;
        *(uint32_t*)&yl[i0] = l0v;
        *(uint32_t*)&yh[i1] = h1;
        *(uint32_t*)&yl[i1] = l1v;
    }
#undef STAGE_KV
}

// ---------------------------------------------------------------------------
// Launch
// ---------------------------------------------------------------------------
extern "C" void kernel_launch(void* const* d_in, const int* in_sizes, int n_in,
                              void* d_out, int out_size)
{
    const float* x     = (const float*)d_in[0];
    const float* Wqkv  = (const float*)d_in[1];
    const float* Wproj = (const float*)d_in[2];
    float* out = (float*)d_out;

    const int gemm_smem = (4 * SA_SZ + 4 * SB_SZ) * sizeof(__nv_bfloat16);
    const int attn_smem = 2 * SMBUF * sizeof(__nv_bfloat16);
    cudaFuncSetAttribute(gemm_bf16x3<true>,  cudaFuncAttributeMaxDynamicSharedMemorySize, gemm_smem);
    cudaFuncSetAttribute(gemm_bf16x3<false>, cudaFuncAttributeMaxDynamicSharedMemorySize, gemm_smem);
    cudaFuncSetAttribute(attn_mma, cudaFuncAttributeMaxDynamicSharedMemorySize, attn_smem);

    __nv_bfloat16 *d_ah, *d_al, *d_bh, *d_bl, *d_qh, *d_ql;
    cudaGetSymbolAddress((void**)&d_ah, g_ah);
    cudaGetSymbolAddress((void**)&d_al, g_al);
    cudaGetSymbolAddress((void**)&d_bh, g_bh);
    cudaGetSymbolAddress((void**)&d_bl, g_bl);
    cudaGetSymbolAddress((void**)&d_qh, g_qh);
    cudaGetSymbolAddress((void**)&d_ql, g_ql);

    // 1) split x, Wqkv
    {
        int n4 = MROWS * Cc / 4;
        split_kernel<<<(n4 + 255) / 256, 256>>>(x, d_ah, d_al, n4);
        int w4 = Cc * N_QKV / 4;
        split_kernel<<<(w4 + 255) / 256, 256>>>(Wqkv, d_bh, d_bl, w4);
    }
    // 2) QKV GEMM -> bf16 hi/lo qkv directly
    {
        dim3 grid(N_QKV / GBN, MROWS / GBM);
        gemm_bf16x3<true><<<grid, 256, gemm_smem>>>(d_ah, d_al, d_bh, d_bl,
                                                    nullptr, d_qh, d_ql,
                                                    MROWS, N_QKV, Cc);
    }
    // 3) attention -> y hi/lo directly into A buffers
    {
        dim3 grid(Tt / 64, Bb * Hh);
        attn_mma<<<grid, 128, attn_smem>>>(d_qh, d_ql, d_ah, d_al);
    }
    // 4) split Wproj; projection GEMM -> fp32 out
    {
        int w4 = Cc * Cc / 4;
        split_kernel<<<(w4 + 255) / 256, 256>>>(Wproj, d_bh, d_bl, w4);
        dim3 grid(Cc / GBN, MROWS / GBM);
        gemm_bf16x3<false><<<grid, 256, gemm_smem>>>(d_ah, d_al, d_bh, d_bl,
                                                     out, nullptr, nullptr,
                                                     MROWS, Cc, Cc);
    }
}